// round 3
// baseline (speedup 1.0000x reference)
#include <cuda_runtime.h>

// FoldNd (col2im): B=16, C=64, K=3, H=W=128, PAD=1, STR=1, DIL=1
// Gather form, 8 output pixels per thread (2x float4), streaming cache hints.
//
// out[b,c,h,w] = sum_{kh,kw} in[(b*64+c)*9 + kh*3+kw][ (h+1-kh)*128 + (w+1-kw) ]

namespace {
constexpr int H = 128;
constexpr int W = 128;
constexpr int PLANE = H * W;            // 16384
constexpr int NOUT = 16 * 64 * H * W;   // 16,777,216
constexpr int NTHREADS_TOTAL = NOUT / 8; // 2,097,152
}

__global__ void __launch_bounds__(256) fold_vec8_kernel(
    const float* __restrict__ in, float* __restrict__ out)
{
    int v = blockIdx.x * blockDim.x + threadIdx.x;
    if (v >= NTHREADS_TOTAL) return;

    int w0 = (v & 15) << 3;          // 0,8,...,120
    int h  = (v >> 4) & (H - 1);
    int bc = v >> 11;                // b*64 + c

    const float* base = in + (long long)bc * 9 * PLANE;

    float acc[8];
    #pragma unroll
    for (int j = 0; j < 8; ++j) acc[j] = 0.f;

    #pragma unroll
    for (int kh = 0; kh < 3; ++kh) {
        int lh = h + 1 - kh;
        if ((unsigned)lh < (unsigned)H) {
            const float* r0 = base + (kh * 3 + 0) * PLANE + lh * W; // kw=0
            const float* r1 = r0 + PLANE;                            // kw=1
            const float* r2 = r1 + PLANE;                            // kw=2

            // batched streaming vector loads (48B/plane-row segment)
            float4 A0 = __ldcs(reinterpret_cast<const float4*>(r0 + w0));
            float4 A1 = __ldcs(reinterpret_cast<const float4*>(r0 + w0 + 4));
            float4 B0 = __ldcs(reinterpret_cast<const float4*>(r1 + w0));
            float4 B1 = __ldcs(reinterpret_cast<const float4*>(r1 + w0 + 4));
            float4 C0 = __ldcs(reinterpret_cast<const float4*>(r2 + w0));
            float4 C1 = __ldcs(reinterpret_cast<const float4*>(r2 + w0 + 4));
            // boundary scalars (these lines are shared with neighbor threads -> L1/L2 hit)
            float a8  = (w0 < W - 8) ? __ldg(r0 + w0 + 8) : 0.f; // kw=0, lw=w0+8
            float cm1 = (w0 > 0)     ? __ldg(r2 + w0 - 1) : 0.f; // kw=2, lw=w0-1

            // output w0+j: kw0 -> elem(w0+j+1), kw1 -> elem(w0+j), kw2 -> elem(w0+j-1)
            acc[0] += A0.y + B0.x + cm1;
            acc[1] += A0.z + B0.y + C0.x;
            acc[2] += A0.w + B0.z + C0.y;
            acc[3] += A1.x + B0.w + C0.z;
            acc[4] += A1.y + B1.x + C0.w;
            acc[5] += A1.z + B1.y + C1.x;
            acc[6] += A1.w + B1.z + C1.y;
            acc[7] += a8  + B1.w + C1.z;
        }
    }

    float4 o0 = make_float4(acc[0], acc[1], acc[2], acc[3]);
    float4 o1 = make_float4(acc[4], acc[5], acc[6], acc[7]);
    __stcs(reinterpret_cast<float4*>(out) + 2 * v,     o0);
    __stcs(reinterpret_cast<float4*>(out) + 2 * v + 1, o1);
}

extern "C" void kernel_launch(void* const* d_in, const int* in_sizes, int n_in,
                              void* d_out, int out_size)
{
    const float* in = (const float*)d_in[0];
    float* out = (float*)d_out;
    const int threads = 256;
    const int blocks = (NTHREADS_TOTAL + threads - 1) / threads;
    fold_vec8_kernel<<<blocks, threads>>>(in, out);
}

// round 4
// speedup vs baseline: 1.0377x; 1.0377x over previous
#include <cuda_runtime.h>

// FoldNd (col2im): B=16, C=64, K=3, H=W=128, PAD=1, STR=1, DIL=1
// Gather form, vec4 per thread. One warp = one full output row (32 lanes x 4px),
// so the boundary elements (lw = w0-1 and lw = w0+4) are exchanged via warp
// shuffle instead of scalar loads: 9 aligned LDG.128 per thread total, 0 scalar
// loads. kh-predicate is warp-uniform (depends only on h).

namespace {
constexpr int H = 128;
constexpr int W = 128;
constexpr int PLANE = H * W;            // 16384
constexpr int NOUT = 16 * 64 * H * W;   // 16,777,216
constexpr int NVEC = NOUT / 4;          // 4,194,304
}

__global__ void __launch_bounds__(256) fold_vec4_shfl_kernel(
    const float* __restrict__ in, float* __restrict__ out)
{
    int v = blockIdx.x * blockDim.x + threadIdx.x;
    if (v >= NVEC) return;

    int lane = v & 31;
    int w0 = lane << 2;              // 0,4,...,124 (warp spans one row)
    int h  = (v >> 5) & (H - 1);
    int bc = v >> 12;                // b*64 + c

    const float* base = in + (long long)bc * 9 * PLANE;

    float4 acc = make_float4(0.f, 0.f, 0.f, 0.f);

    #pragma unroll
    for (int kh = 0; kh < 3; ++kh) {
        int lh = h + 1 - kh;         // warp-uniform
        if ((unsigned)lh < (unsigned)H) {
            const float* r0 = base + (kh * 3 + 0) * PLANE + lh * W; // kw=0
            const float* r1 = r0 + PLANE;                            // kw=1
            const float* r2 = r1 + PLANE;                            // kw=2

            float4 A  = __ldg(reinterpret_cast<const float4*>(r0 + w0));
            float4 Bv = __ldg(reinterpret_cast<const float4*>(r1 + w0));
            float4 Cv = __ldg(reinterpret_cast<const float4*>(r2 + w0));

            // a4  = r0[w0+4]  = next lane's A.x   (lane 31: lw=128 -> 0)
            // cm1 = r2[w0-1]  = prev lane's Cv.w  (lane 0:  lw=-1  -> 0)
            float a4  = __shfl_down_sync(0xFFFFFFFFu, A.x, 1);
            float cm1 = __shfl_up_sync(0xFFFFFFFFu, Cv.w, 1);
            if (lane == 31) a4  = 0.f;
            if (lane == 0)  cm1 = 0.f;

            // output w0+j: kw0 -> elem(w0+j+1), kw1 -> elem(w0+j), kw2 -> elem(w0+j-1)
            acc.x += A.y + Bv.x + cm1;
            acc.y += A.z + Bv.y + Cv.x;
            acc.z += A.w + Bv.z + Cv.y;
            acc.w += a4  + Bv.w + Cv.z;
        }
    }

    __stcs(reinterpret_cast<float4*>(out) + v, acc);
}

extern "C" void kernel_launch(void* const* d_in, const int* in_sizes, int n_in,
                              void* d_out, int out_size)
{
    const float* in = (const float*)d_in[0];
    float* out = (float*)d_out;
    const int threads = 256;
    const int blocks = (NVEC + threads - 1) / threads;
    fold_vec4_shfl_kernel<<<blocks, threads>>>(in, out);
}